// round 9
// baseline (speedup 1.0000x reference)
#include <cuda_runtime.h>
#include <cstdint>
#include <cstddef>

#define BB 64
#define TT 512
#define II 1024
#define HH 1024

typedef unsigned long long ull;

// ---------------- scratch (device globals; no cudaMalloc allowed) ----------------
__device__ float g_xw[(size_t)BB * TT * HH];   // 128 MiB: xw = x@W^T + bW
__device__ float g_h3[2][(size_t)BB * HH];     // ping-pong h3 exchange
__device__ unsigned g_cnt[128];                // per-b-group counters (slot bt*32)

// ---------------- helpers ----------------
__device__ __forceinline__ void ffma2(ull &d, ull a, ull b) {
    asm("fma.rn.f32x2 %0, %1, %2, %0;" : "+l"(d) : "l"(a), "l"(b));
}
__device__ __forceinline__ float lohi_sum(ull v) {
    float lo, hi;
    asm("mov.b64 {%0, %1}, %2;" : "=f"(lo), "=f"(hi) : "l"(v));
    return lo + hi;
}
__device__ __forceinline__ float hw_tanh(float x) {
    float r;
    asm("tanh.approx.f32 %0, %1;" : "=f"(r) : "f"(x));
    return r;
}

// =====================================================================
// Kernel 1: xw = x @ W^T + bW.  (unchanged; + counter reset)
// =====================================================================
#define G_STR 36

__global__ __launch_bounds__(256, 2) void gemm1_kernel(
    const float* __restrict__ x, const float* __restrict__ W,
    const float* __restrict__ bW)
{
    if (blockIdx.x == 0 && blockIdx.y == 0 && threadIdx.x < 128)
        g_cnt[threadIdx.x] = 0u;

    __shared__ float As[2][64 * G_STR];
    __shared__ float Bs[2][64 * G_STR];

    const int tid = threadIdx.x;
    const int m_blk = blockIdx.y * 64, n_blk = blockIdx.x * 64;
    const int w = tid >> 5, l = tid & 31;
    const int wm = (w & 3) * 16, wn = (w >> 2) * 32;
    const int lm = l & 3, ln = l >> 2;
    const int lrow = tid >> 2, lcol = (tid & 3) * 4;

    const float* xp = &x[(size_t)(m_blk + lrow) * II + lcol];
    const float* wp = &W[(size_t)(n_blk + lrow) * II + lcol];

    ull acc[4][4];
#pragma unroll
    for (int i = 0; i < 4; ++i)
#pragma unroll
        for (int j = 0; j < 4; ++j) acc[i][j] = 0ULL;

    {
        float4 xa = *(const float4*)xp;
        float4 xb = *(const float4*)(xp + 16);
        float4 wa = *(const float4*)wp;
        float4 wb = *(const float4*)(wp + 16);
        *(float4*)&As[0][lrow * G_STR + lcol]      = xa;
        *(float4*)&As[0][lrow * G_STR + lcol + 16] = xb;
        *(float4*)&Bs[0][lrow * G_STR + lcol]      = wa;
        *(float4*)&Bs[0][lrow * G_STR + lcol + 16] = wb;
    }
    __syncthreads();

    for (int it = 0; it < II / 32; ++it) {
        const int cur = it & 1, nxt = cur ^ 1;
        float4 xa, xb, wa, wb;
        const bool more = (it + 1) < II / 32;
        if (more) {
            const int kk = (it + 1) * 32;
            xa = *(const float4*)(xp + kk);
            xb = *(const float4*)(xp + kk + 16);
            wa = *(const float4*)(wp + kk);
            wb = *(const float4*)(wp + kk + 16);
        }
#pragma unroll
        for (int kq = 0; kq < 8; ++kq) {
            ulonglong2 a[4], b[4];
#pragma unroll
            for (int i = 0; i < 4; ++i)
                a[i] = *(const ulonglong2*)&As[cur][(wm + lm + 4 * i) * G_STR + kq * 4];
#pragma unroll
            for (int j = 0; j < 4; ++j)
                b[j] = *(const ulonglong2*)&Bs[cur][(wn + ln + 8 * j) * G_STR + kq * 4];
#pragma unroll
            for (int i = 0; i < 4; ++i)
#pragma unroll
                for (int j = 0; j < 4; ++j) {
                    ffma2(acc[i][j], a[i].x, b[j].x);
                    ffma2(acc[i][j], a[i].y, b[j].y);
                }
        }
        if (more) {
            *(float4*)&As[nxt][lrow * G_STR + lcol]      = xa;
            *(float4*)&As[nxt][lrow * G_STR + lcol + 16] = xb;
            *(float4*)&Bs[nxt][lrow * G_STR + lcol]      = wa;
            *(float4*)&Bs[nxt][lrow * G_STR + lcol + 16] = wb;
        }
        __syncthreads();
    }

    float bwv[4];
#pragma unroll
    for (int j = 0; j < 4; ++j) bwv[j] = bW[n_blk + wn + ln + 8 * j];
#pragma unroll
    for (int i = 0; i < 4; ++i) {
        const size_t row = (size_t)(m_blk + wm + lm + 4 * i) * HH + n_blk + wn + ln;
#pragma unroll
        for (int j = 0; j < 4; ++j)
            g_xw[row + 8 * j] = lohi_sum(acc[i][j]) + bwv[j];
    }
}

// =====================================================================
// Kernel 2: persistent scan, h3-exchange, 1024 threads (32 warps, occ 50%).
// 128 CTAs = 4 b-groups x 32 n-tiles (32 cols each).
// Phase B: 32 warps = 16 k-sixteenths x 2 b-halves; lane owns 2b x 4n
//          f32x2 accs over a 64-wide k-range; 16 k-partials via smem.
// red layout: [16][16][32] with XOR swizzle col' = (col + 8*row) & 31
//   -> writer banks (ln + 8*lb + 8*j) mod 32 distinct: conflict-free STS
//   -> reader (row fixed, col=nl 0..31): consecutive banks: conflict-free
// =====================================================================
#define U_STR 1028                 // 16B-group = n mod 8 -> conflict-free uv
#define H_STR 1032                 // 16B-group = 2b mod 8 -> broadcast hv
#define RED_OFF (32 * U_STR + 16 * H_STR)          // 49408 floats
#define SMEM_SCAN ((RED_OFF + 16 * 512) * 4)       // 230400 bytes

__global__ __launch_bounds__(1024, 1) void scan_kernel(
    const float* __restrict__ U, const float* __restrict__ bU,
    float* __restrict__ out1, float* __restrict__ out2)
{
    extern __shared__ float smem[];
    float* Us  = smem;               // [32][U_STR]
    float* h3s = smem + 32 * U_STR;  // [16][H_STR]
    float* red = smem + RED_OFF;     // [16][16][32] swizzled

    const int tid = threadIdx.x;
    const int bt = blockIdx.x >> 5, nt = blockIdx.x & 31;
    const int b0 = bt * 16, n0 = nt * 32;
    unsigned* cnt = &g_cnt[bt * 32];

    // load U slice (rows n0..n0+31) once
    for (int i = tid; i < 32 * 256; i += 1024) {
        int r = i >> 8, c = (i & 255) * 4;
        *(float4*)&Us[r * U_STR + c] = *(const float4*)&U[(size_t)(n0 + r) * HH + c];
    }

    // output mapping (threads 0..511 only): one element each
    const int bi = tid >> 5;              // 0..15 for tid<512
    const int nl = tid & 31;
    const float bu = (tid < 512) ? bU[n0 + nl] : 0.0f;
    const unsigned orow = (unsigned)(b0 + bi) * TT * HH + n0 + nl;  // out1 base
    const unsigned hrow = (unsigned)(b0 + bi) * HH + n0 + nl;       // g_h3 index
    const int rcol = (nl + 8 * bi) & 31;  // swizzled read column

    // Phase-B mapping: 32 warps = 16 k-sixteenths x 2 b-halves
    const int w = tid >> 5, l = tid & 31;
    const int wk = w >> 1;                // 0..15
    const int wb = (w & 1) * 8;           // b-half base
    const int lb = l & 3, ln = l >> 2;
    const int k0 = wk * 64;

    // h3 staging: warp stages rows wb..wb+7, cols k0..k0+63
    const int sr = wb + (l >> 2);
    const int sc = k0 + (l & 3) * 16;

    // ---- bootstrap: h3[0] = tanh(xw[0]) ----
    if (tid < 512) {
        float h = hw_tanh(g_xw[orow]);
        g_h3[0][hrow] = h;
        out1[orow] = h;
    }
    __syncthreads();
    if (tid == 0) { __threadfence(); atomicAdd(cnt, 1u); }

    for (int t = 0; t < TT - 1; ++t) {
        // ---- wait for h3[t] from all 32 CTAs of this b-group ----
        if (tid == 0) {
            const unsigned target = 32u * (unsigned)(t + 1);
            while (*(volatile unsigned*)cnt < target) {}
            __threadfence();
        }
        __syncthreads();

        // prefetch xw[t+1] for own output element
        const float xwv = (tid < 512) ? g_xw[orow + (unsigned)(t + 1) * HH] : 0.0f;

        // ---- stage own h3 patch ----
        {
            const float* hsrc = &g_h3[t & 1][(unsigned)(b0 + sr) * HH];
#pragma unroll
            for (int j = 0; j < 4; ++j) {
                float4 hv = *(const float4*)&hsrc[sc + j * 4];
                *(float4*)&h3s[sr * H_STR + sc + j * 4] = hv;
            }
        }
        __syncwarp();

        // ---- Phase B: partials over this warp's 64-wide k-range ----
        ull acc[2][4];
#pragma unroll
        for (int i = 0; i < 2; ++i)
#pragma unroll
            for (int j = 0; j < 4; ++j) acc[i][j] = 0ULL;

#pragma unroll
        for (int kq = 0; kq < 16; ++kq) {
            const int k = k0 + kq * 4;
            ulonglong2 hv0 = *(const ulonglong2*)&h3s[(wb + lb) * H_STR + k];
            ulonglong2 hv1 = *(const ulonglong2*)&h3s[(wb + lb + 4) * H_STR + k];
            ulonglong2 uv[4];
#pragma unroll
            for (int j = 0; j < 4; ++j)
                uv[j] = *(const ulonglong2*)&Us[(ln + 8 * j) * U_STR + k];
#pragma unroll
            for (int j = 0; j < 4; ++j) {
                ffma2(acc[0][j], hv0.x, uv[j].x);
                ffma2(acc[0][j], hv0.y, uv[j].y);
                ffma2(acc[1][j], hv1.x, uv[j].x);
                ffma2(acc[1][j], hv1.y, uv[j].y);
            }
        }
        // swizzled conflict-free stores: col' = (col + 8*row) & 31
#pragma unroll
        for (int i = 0; i < 2; ++i) {
            const int row = wb + lb + 4 * i;
#pragma unroll
            for (int j = 0; j < 4; ++j) {
                const int col = ln + 8 * j;
                red[wk * 512 + row * 32 + ((col + 8 * row) & 31)] =
                    lohi_sum(acc[i][j]);
            }
        }
        __syncthreads();

        // ---- reduce 16 partials, fuse bias + xw + tanh, publish ----
        if (tid < 512) {
            float s = bu;
#pragma unroll
            for (int p = 0; p < 16; ++p)
                s += red[p * 512 + bi * 32 + rcol];
            const float h = hw_tanh(s + xwv);
            g_h3[(t + 1) & 1][hrow] = h;
            out1[orow + (unsigned)(t + 1) * HH] = h;
            if (t == TT - 2) out2[hrow] = h;
        }
        __syncthreads();
        if (tid == 0) { __threadfence(); atomicAdd(cnt, 1u); }
    }
}

// =====================================================================
// launch
// =====================================================================
extern "C" void kernel_launch(void* const* d_in, const int* in_sizes, int n_in,
                              void* d_out, int out_size)
{
    const float* x  = (const float*)d_in[0];
    const float* W  = (const float*)d_in[1];
    const float* bW = (const float*)d_in[2];
    const float* U  = (const float*)d_in[3];
    const float* bU = (const float*)d_in[4];

    float* out1 = (float*)d_out;
    float* out2 = out1 + (size_t)BB * TT * HH;

    cudaFuncSetAttribute(scan_kernel,
                         cudaFuncAttributeMaxDynamicSharedMemorySize, SMEM_SCAN);

    dim3 g1(HH / 64, (BB * TT) / 64);   // (16, 512)
    gemm1_kernel<<<g1, 256>>>(x, W, bW);
    scan_kernel<<<128, 1024, SMEM_SCAN>>>(U, bU, out1, out2);
}

// round 10
// speedup vs baseline: 1.1812x; 1.1812x over previous
#include <cuda_runtime.h>
#include <cstdint>
#include <cstddef>

#define BB 64
#define TT 512
#define II 1024
#define HH 1024

typedef unsigned long long ull;

// ---------------- scratch (device globals; no cudaMalloc allowed) ----------------
__device__ float g_xw[(size_t)BB * TT * HH];   // 128 MiB: xw = x@W^T + bW
__device__ float g_h3[2][(size_t)BB * HH];     // ping-pong h3 exchange
__device__ unsigned g_cnt[128];                // per-b-group counters (slot bt*32)

// ---------------- helpers ----------------
__device__ __forceinline__ void ffma2(ull &d, ull a, ull b) {
    asm("fma.rn.f32x2 %0, %1, %2, %0;" : "+l"(d) : "l"(a), "l"(b));
}
__device__ __forceinline__ float lohi_sum(ull v) {
    float lo, hi;
    asm("mov.b64 {%0, %1}, %2;" : "=f"(lo), "=f"(hi) : "l"(v));
    return lo + hi;
}
__device__ __forceinline__ float hw_tanh(float x) {
    float r;
    asm("tanh.approx.f32 %0, %1;" : "=f"(r) : "f"(x));
    return r;
}

// =====================================================================
// Kernel 1: xw = x @ W^T + bW. (unchanged; + counter reset)
// =====================================================================
#define G_STR 36

__global__ __launch_bounds__(256, 2) void gemm1_kernel(
    const float* __restrict__ x, const float* __restrict__ W,
    const float* __restrict__ bW)
{
    if (blockIdx.x == 0 && blockIdx.y == 0 && threadIdx.x < 128)
        g_cnt[threadIdx.x] = 0u;

    __shared__ float As[2][64 * G_STR];
    __shared__ float Bs[2][64 * G_STR];

    const int tid = threadIdx.x;
    const int m_blk = blockIdx.y * 64, n_blk = blockIdx.x * 64;
    const int w = tid >> 5, l = tid & 31;
    const int wm = (w & 3) * 16, wn = (w >> 2) * 32;
    const int lm = l & 3, ln = l >> 2;
    const int lrow = tid >> 2, lcol = (tid & 3) * 4;

    const float* xp = &x[(size_t)(m_blk + lrow) * II + lcol];
    const float* wp = &W[(size_t)(n_blk + lrow) * II + lcol];

    ull acc[4][4];
#pragma unroll
    for (int i = 0; i < 4; ++i)
#pragma unroll
        for (int j = 0; j < 4; ++j) acc[i][j] = 0ULL;

    {
        float4 xa = *(const float4*)xp;
        float4 xb = *(const float4*)(xp + 16);
        float4 wa = *(const float4*)wp;
        float4 wb = *(const float4*)(wp + 16);
        *(float4*)&As[0][lrow * G_STR + lcol]      = xa;
        *(float4*)&As[0][lrow * G_STR + lcol + 16] = xb;
        *(float4*)&Bs[0][lrow * G_STR + lcol]      = wa;
        *(float4*)&Bs[0][lrow * G_STR + lcol + 16] = wb;
    }
    __syncthreads();

    for (int it = 0; it < II / 32; ++it) {
        const int cur = it & 1, nxt = cur ^ 1;
        float4 xa, xb, wa, wb;
        const bool more = (it + 1) < II / 32;
        if (more) {
            const int kk = (it + 1) * 32;
            xa = *(const float4*)(xp + kk);
            xb = *(const float4*)(xp + kk + 16);
            wa = *(const float4*)(wp + kk);
            wb = *(const float4*)(wp + kk + 16);
        }
#pragma unroll
        for (int kq = 0; kq < 8; ++kq) {
            ulonglong2 a[4], b[4];
#pragma unroll
            for (int i = 0; i < 4; ++i)
                a[i] = *(const ulonglong2*)&As[cur][(wm + lm + 4 * i) * G_STR + kq * 4];
#pragma unroll
            for (int j = 0; j < 4; ++j)
                b[j] = *(const ulonglong2*)&Bs[cur][(wn + ln + 8 * j) * G_STR + kq * 4];
#pragma unroll
            for (int i = 0; i < 4; ++i)
#pragma unroll
                for (int j = 0; j < 4; ++j) {
                    ffma2(acc[i][j], a[i].x, b[j].x);
                    ffma2(acc[i][j], a[i].y, b[j].y);
                }
        }
        if (more) {
            *(float4*)&As[nxt][lrow * G_STR + lcol]      = xa;
            *(float4*)&As[nxt][lrow * G_STR + lcol + 16] = xb;
            *(float4*)&Bs[nxt][lrow * G_STR + lcol]      = wa;
            *(float4*)&Bs[nxt][lrow * G_STR + lcol + 16] = wb;
        }
        __syncthreads();
    }

    float bwv[4];
#pragma unroll
    for (int j = 0; j < 4; ++j) bwv[j] = bW[n_blk + wn + ln + 8 * j];
#pragma unroll
    for (int i = 0; i < 4; ++i) {
        const size_t row = (size_t)(m_blk + wm + lm + 4 * i) * HH + n_blk + wn + ln;
#pragma unroll
        for (int j = 0; j < 4; ++j)
            g_xw[row + 8 * j] = lohi_sum(acc[i][j]) + bwv[j];
    }
}

// =====================================================================
// Kernel 2: persistent scan, U-IN-REGISTERS formulation.
// 128 CTAs = 4 b-groups x 32 n-tiles, 512 threads (16 warps).
// Warp w owns k-chunk [64w, 64w+64); lane l owns column n = n0 + l and
// holds U[n][k-chunk] in 32 ull registers for all 512 steps.
// Per step: stage h3[t] (16b x 1024k) into smem once; each lane then
// consumes it via BROADCAST LDS.128 (1 wavefront each), 32 FFMA2 per b.
// Partials red[w][b][l] reduced by output thread (bi, nl) = (tid>>5, tid&31).
// =====================================================================
#define H_STR 1024
#define RED_OFF (16 * H_STR)
#define SMEM_SCAN ((RED_OFF + 16 * 16 * 32) * 4)   // 98304 bytes

__global__ __launch_bounds__(512, 1) void scan_kernel(
    const float* __restrict__ U, const float* __restrict__ bU,
    float* __restrict__ out1, float* __restrict__ out2)
{
    extern __shared__ float smem[];
    float* h3s = smem;               // [16][1024]
    float* red = smem + RED_OFF;     // [16][16][32]

    const int tid = threadIdx.x;
    const int bt = blockIdx.x >> 5, nt = blockIdx.x & 31;
    const int b0 = bt * 16, n0 = nt * 32;
    unsigned* cnt = &g_cnt[bt * 32];

    const int w = tid >> 5, l = tid & 31;
    const int k0 = w * 64;                 // this warp's k-chunk

    // ---- load this lane's U slice into registers (once) ----
    ull u[32];
    {
        const float* up = &U[(size_t)(n0 + l) * HH + k0];
#pragma unroll
        for (int j = 0; j < 16; ++j) {
            ulonglong2 v = *(const ulonglong2*)(up + 4 * j);
            u[2 * j]     = v.x;
            u[2 * j + 1] = v.y;
        }
    }

    // output mapping: one element per thread (exactly 512 outputs)
    const int bi = tid >> 5;               // 0..15
    const int nl = tid & 31;               // 0..31
    const float bu = bU[n0 + nl];
    const unsigned orow = (unsigned)(b0 + bi) * TT * HH + n0 + nl;
    const unsigned hrow = (unsigned)(b0 + bi) * HH + n0 + nl;

    // ---- bootstrap: h3[0] = tanh(xw[0]) ----
    {
        float h = hw_tanh(g_xw[orow]);
        g_h3[0][hrow] = h;
        out1[orow] = h;
    }
    __syncthreads();
    if (tid == 0) { __threadfence(); atomicAdd(cnt, 1u); }

    for (int t = 0; t < TT - 1; ++t) {
        // prefetch xw[t+1] (independent of barrier; lands during wait)
        const float xwv = g_xw[orow + (unsigned)(t + 1) * HH];

        // ---- wait for h3[t] from all 32 CTAs of this b-group ----
        if (tid == 0) {
            const unsigned target = 32u * (unsigned)(t + 1);
            while (*(volatile unsigned*)cnt < target) {}
            __threadfence();
        }
        __syncthreads();

        // ---- stage h3[t] tile (16 x 1024) into smem, coalesced ----
        {
            const float* hsrc = &g_h3[t & 1][(size_t)b0 * HH];
#pragma unroll
            for (int i = 0; i < 8; ++i) {
                const int idx = tid + i * 512;          // float4 index
                const int row = idx >> 8, col = (idx & 255) * 4;
                float4 hv = *(const float4*)&hsrc[(size_t)row * HH + col];
                *(float4*)&h3s[row * H_STR + col] = hv;
            }
        }
        __syncthreads();

        // ---- Phase B: lane computes its n over its warp's k-chunk ----
#pragma unroll 4
        for (int b = 0; b < 16; ++b) {
            ull a0 = 0ULL, a1 = 0ULL;
            const float* hb = &h3s[b * H_STR + k0];
#pragma unroll
            for (int q = 0; q < 8; ++q) {
                ulonglong2 h01 = *(const ulonglong2*)(hb + 8 * q);      // broadcast
                ulonglong2 h23 = *(const ulonglong2*)(hb + 8 * q + 4);  // broadcast
                ffma2(a0, h01.x, u[4 * q]);
                ffma2(a1, h01.y, u[4 * q + 1]);
                ffma2(a0, h23.x, u[4 * q + 2]);
                ffma2(a1, h23.y, u[4 * q + 3]);
            }
            red[(w * 16 + b) * 32 + l] = lohi_sum(a0) + lohi_sum(a1);
        }
        __syncthreads();

        // ---- reduce 16 warp-partials, fuse bias + xw + tanh, publish ----
        {
            float s = bu;
#pragma unroll
            for (int p = 0; p < 16; ++p)
                s += red[(p * 16 + bi) * 32 + nl];
            const float h = hw_tanh(s + xwv);
            g_h3[(t + 1) & 1][hrow] = h;
            out1[orow + (unsigned)(t + 1) * HH] = h;
            if (t == TT - 2) out2[hrow] = h;
        }
        __syncthreads();
        if (tid == 0) { __threadfence(); atomicAdd(cnt, 1u); }
    }
}

// =====================================================================
// launch
// =====================================================================
extern "C" void kernel_launch(void* const* d_in, const int* in_sizes, int n_in,
                              void* d_out, int out_size)
{
    const float* x  = (const float*)d_in[0];
    const float* W  = (const float*)d_in[1];
    const float* bW = (const float*)d_in[2];
    const float* U  = (const float*)d_in[3];
    const float* bU = (const float*)d_in[4];

    float* out1 = (float*)d_out;
    float* out2 = out1 + (size_t)BB * TT * HH;

    cudaFuncSetAttribute(scan_kernel,
                         cudaFuncAttributeMaxDynamicSharedMemorySize, SMEM_SCAN);

    dim3 g1(HH / 64, (BB * TT) / 64);   // (16, 512)
    gemm1_kernel<<<g1, 256>>>(x, W, bW);
    scan_kernel<<<128, 512, SMEM_SCAN>>>(U, bU, out1, out2);
}